// round 13
// baseline (speedup 1.0000x reference)
#include <cuda_runtime.h>
#include <math.h>

#define BB 32
#define SS 2048
#define EE 1024
#define RR 512
#define NSTEPS 8
#define MIDG 128
#define MIDT 512

// ---------------- device state (no allocations allowed) ----------------
__device__ float g_mean[BB*EE];
__device__ float g_cur[BB*RR];
__device__ float g_h[BB*RR];
__device__ float g_c[BB*RR];
__device__ float g_hsum[BB*RR];
__device__ float g_rout[BB*EE];
__device__ float g_Wsum[4*RR*RR];         // W_ih + W_hh  [2048][512]
__device__ int   g_encQ[RR*EE/4];         // ternary enc weights, packed int8x4
__device__ int   g_decQ[EE*RR/4];         // ternary dec weights, packed int8x4
__device__ float g_encpart[32], g_decpart[32];
__device__ float g_sum_gate;
__device__ int   g_trig[NSTEPS];
// per-block max slots (no same-address atomics anywhere)
__device__ float g_maxmean_p[MIDG];
__device__ float g_maxh_p[NSTEPS][MIDG];
__device__ float g_maxhsum_p[MIDG];
// flag-array grid barrier; monotonic counters -> replay-safe, no reset
__device__ int   g_flags[MIDG];

// ---------------- helpers ----------------
__device__ __forceinline__ float warpRedSum(float v){
    #pragma unroll
    for (int o=16;o;o>>=1) v += __shfl_xor_sync(0xffffffffu, v, o);
    return v;
}
__device__ __forceinline__ float warpRedMax(float v){
    #pragma unroll
    for (int o=16;o;o>>=1) v = fmaxf(v, __shfl_xor_sync(0xffffffffu, v, o));
    return v;
}
__device__ __forceinline__ float sigm(float x){ return 1.f/(1.f+expf(-x)); }
__device__ __forceinline__ float terx(float a, float w, float thr){
    float s = (w > 0.f) ? a : -a;
    return (fabsf(w) > thr) ? s : 0.f;
}
__device__ __forceinline__ float quantz(float x, float is){
    return fminf(fmaxf(rintf(x/is), -128.f), 127.f);
}
__device__ __forceinline__ int tern1(float w, float thr){
    int s = (w > 0.f) ? 1 : -1;
    return (fabsf(w) > thr) ? s : 0;
}
__device__ __forceinline__ int pack4(int a, int b, int c, int d){
    return (a & 0xff) | ((b & 0xff) << 8) | ((c & 0xff) << 16) | (d << 24);
}
// packed fp32x2 FMA: d.lo += a.lo*b.lo ; d.hi += a.hi*b.hi  (exact fp32 math)
__device__ __forceinline__ void fma2(unsigned long long &d, unsigned long long a, unsigned long long b){
    asm("fma.rn.f32x2 %0, %1, %2, %0;" : "+l"(d) : "l"(a), "l"(b));
}
__device__ __forceinline__ float f2sum(unsigned long long v){
    return __uint_as_float((unsigned)(v & 0xffffffffull)) + __uint_as_float((unsigned)(v >> 32));
}
// flag-array grid barrier: arrival = parallel STG to own slot; poll = ldcg min-reduce.
// __threadfence (gpu scope) flushes L1 -> cross-block data fresh after the bar.
__device__ __forceinline__ void gbar(int t, int blk, int target){
    __syncthreads();
    if (t == 0){
        __threadfence();
        g_flags[blk] = target;
        int4* fp = (int4*)g_flags;
        for(;;){
            int mn = 0x7fffffff;
            #pragma unroll
            for (int i=0;i<MIDG/4;i++){
                int4 v = __ldcg(fp + i);
                mn = min(mn, min(min(v.x,v.y), min(v.z,v.w)));
            }
            if (mn >= target) break;
            __nanosleep(128);
        }
        __threadfence();
    }
    __syncthreads();
}

// ---------------- K_init: Wsum + |W| sums + gate sum + zero state ----------------
__global__ void k_init(const float* __restrict__ Wih, const float* __restrict__ Whh,
                       const float* __restrict__ encW, const float* __restrict__ decW,
                       const float* __restrict__ gateW){
    __shared__ float red[8];
    int blk = blockIdx.x, t = threadIdx.x;
    int w = t>>5, lane = t&31;
    if (blk < 1024){
        int gid = blk*256 + t;                    // 262144 float4s of Wsum
        float4 a = ((const float4*)Wih)[gid];
        float4 b = ((const float4*)Whh)[gid];
        float4 s; s.x=a.x+b.x; s.y=a.y+b.y; s.z=a.z+b.z; s.w=a.w+b.w;
        ((float4*)g_Wsum)[gid] = s;
        float4 z; z.x=z.y=z.z=z.w=0.f;
        if      (gid < 4096)  ((float4*)g_h)[gid] = z;
        else if (gid < 8192)  ((float4*)g_c)[gid-4096] = z;
        else if (gid < 12288) ((float4*)g_hsum)[gid-8192] = z;
    } else if (blk < 1088){
        int c = blk - 1024;                       // 0..63
        const float4* Wp = (const float4*)((c<32) ? encW : decW);
        int cc = c & 31;
        float s = 0.f;
        #pragma unroll 4
        for (int i=t;i<4096;i+=256){
            float4 v = Wp[cc*4096+i];
            s += fabsf(v.x)+fabsf(v.y)+fabsf(v.z)+fabsf(v.w);
        }
        s = warpRedSum(s);
        if (lane==0) red[w]=s;
        __syncthreads();
        if (t==0){
            float ss = 0.f;
            #pragma unroll
            for (int i=0;i<8;i++) ss += red[i];
            ((c<32)? g_encpart : g_decpart)[cc] = ss;
        }
    } else {                                      // blk==1088: sum|gate_W|
        float s = fabsf(gateW[t]) + fabsf(gateW[t+256]);
        s = warpRedSum(s);
        if (lane==0) red[w]=s;
        __syncthreads();
        if (t==0){
            float ss = 0.f;
            #pragma unroll
            for (int i=0;i<8;i++) ss += red[i];
            g_sum_gate = ss;
        }
    }
}

// ---------------- K_mid: fused mean+pack+enc+8*lstm+dec ----------------
#define MID_SMEM ((32*516 + 1024 + 64)*4)
__global__ void __launch_bounds__(MIDT,1) k_mid(
    const float* __restrict__ x,
    const float* __restrict__ encW, const float* __restrict__ encB,
    const float* __restrict__ Wih,  const float* __restrict__ bih,
    const float* __restrict__ bhh,
    const float* __restrict__ decW, const float* __restrict__ decB,
    const float* __restrict__ gateW, const float* __restrict__ gateB)
{
    extern __shared__ float sm[];
    float* As  = sm;                 // 32*516 floats
    float* gs  = sm + 32*516;        // 1024 floats
    float* aux = gs + 1024;          // 64 floats
    int t = threadIdx.x, blk = blockIdx.x;
    int w = t>>5, lane = t&31;
    int fbase = 0;
    if (t == 0) fbase = g_flags[blk];             // monotonic base for this launch

    // ===== phase 0a: pack ternary weights (4 f4 per thread) =====
    {
        float se=0.f, sd=0.f;
        #pragma unroll
        for (int i=0;i<32;i++){ se += g_encpart[i]; sd += g_decpart[i]; }
        float thre = 0.5f*se*(1.f/524288.f);
        float thrd = 0.5f*sd*(1.f/524288.f);
        #pragma unroll
        for (int k=0;k<4;k++){
            int gid = blk*2048 + k*MIDT + t;      // 0..262143
            bool isenc = gid < 131072;
            float thr = isenc ? thre : thrd;
            int idx = isenc ? gid : gid - 131072;
            float4 wv = ((const float4*)(isenc ? encW : decW))[idx];
            (isenc ? g_encQ : g_decQ)[idx] =
                pack4(tern1(wv.x,thr), tern1(wv.y,thr), tern1(wv.z,thr), tern1(wv.w,thr));
        }
    }

    // ===== phase 0b: mean over seq for (batch, 256-col chunk) =====
    {
        int b = blk>>2, ec = blk&3;
        const float4* xp = (const float4*)x + (size_t)b*SS*256 + ec*64;
        int row0 = t>>6, col = t&63;              // 8 row groups x 64 f4 cols
        float sx=0.f, sy=0.f, sz=0.f, sw=0.f;
        #pragma unroll 8
        for (int r=row0; r<SS; r+=8){
            float4 v = __ldcs(xp + (size_t)r*256 + col);
            sx+=v.x; sy+=v.y; sz+=v.z; sw+=v.w;
        }
        float4 acc; acc.x=sx; acc.y=sy; acc.z=sz; acc.w=sw;
        ((float4*)sm)[row0*64 + col] = acc;       // [8][256] floats
        __syncthreads();
        float mv = 0.f;
        if (t < 256){
            float s = 0.f;
            #pragma unroll
            for (int p=0;p<8;p++) s += sm[p*256 + t];
            s *= (1.f/2048.f);
            g_mean[b*EE + ec*256 + t] = s;
            mv = fabsf(s);
        }
        mv = warpRedMax(mv);
        if (lane==0) aux[44+w] = mv;
        __syncthreads();
        if (t==0){
            float mm = 0.f;
            #pragma unroll
            for (int i=0;i<8;i++) mm = fmaxf(mm, aux[44+i]);
            g_maxmean_p[blk] = mm;                // per-block slot, no atomics
        }
    }
    gbar(t, blk, fbase+1);

    // ===== phase 1: enc  cur = bit_linear(mean) via dp4a =====
    {
        // reduce 128 per-block maxes
        float mv = 0.f;
        if (t < MIDG) mv = g_maxmean_p[t];
        mv = warpRedMax(mv);
        if (lane==0 && w < 4) aux[40+w] = mv;
        __syncthreads();
        float is = fmaxf(fmaxf(aux[40],aux[41]),fmaxf(aux[42],aux[43])) * (1.f/127.f);

        int* smq = (int*)sm;                      // [32][257] words
        for (int i4=t; i4<8192; i4+=MIDT){
            float4 v = ((const float4*)g_mean)[i4];
            smq[(i4>>8)*257 + (i4&255)] =
                pack4((int)quantz(v.x,is), (int)quantz(v.y,is),
                      (int)quantz(v.z,is), (int)quantz(v.w,is));
        }
        __syncthreads();
        float ssum = 0.f;
        #pragma unroll
        for (int i=0;i<32;i++) ssum += g_encpart[i];
        float wscale = ssum * (1.f/524288.f);
        int r = blk*4 + (w>>2);                   // 4 rows/block, 4 warps/row (K-split)
        int q = w & 3;
        const int4* Wq = (const int4*)(g_encQ + r*256 + q*64);
        const int*  ar = smq + lane*257 + q*64;
        int a0=0,a1=0,a2=0,a3=0;
        #pragma unroll
        for (int k=0;k<16;k++){
            int4 wv = Wq[k];
            a0 = __dp4a(ar[4*k+0], wv.x, a0);
            a1 = __dp4a(ar[4*k+1], wv.y, a1);
            a2 = __dp4a(ar[4*k+2], wv.z, a2);
            a3 = __dp4a(ar[4*k+3], wv.w, a3);
        }
        int* sp = (int*)(sm + 9024);              // 512 ints
        sp[((w>>2)*32+lane)*4 + q] = (a0+a1)+(a2+a3);
        __syncthreads();
        if (t < 128){
            int rr = t>>5, b = t&31;
            int s = sp[(rr*32+b)*4]+sp[(rr*32+b)*4+1]+sp[(rr*32+b)*4+2]+sp[(rr*32+b)*4+3];
            g_cur[b*RR + blk*4+rr] = (float)s*(wscale*is) + encB[blk*4+rr];
        }
    }
    gbar(t, blk, fbase+2);

    // ===== phases 2..9: LSTM steps =====
    for (int step=0; step<NSTEPS; step++){
        const float* Ain = (step==0) ? g_cur : g_h;
        const float* Wp  = (step==0) ? Wih   : g_Wsum;

        for (int i4=t; i4<4096; i4+=MIDT){
            ((float4*)As)[(i4>>7)*129 + (i4&127)] = ((const float4*)Ain)[i4];
        }
        __syncthreads();

        // trigger of step-1 (only steps 3..6 matter -> step>=4)
        if (step >= 4){
            // reduce per-block |h| maxes of previous step
            float mv = 0.f;
            if (t < MIDG) mv = g_maxh_p[step-1][t];
            mv = warpRedMax(mv);
            if (lane==0 && w < 4) aux[40+w] = mv;
            __syncthreads();
            float maxh = fmaxf(fmaxf(aux[40],aux[41]),fmaxf(aux[42],aux[43]));
            float is  = maxh * (1.f/127.f);
            float inv = 1.f / is;
            float gws = g_sum_gate * (1.f/512.f);
            float thr = 0.5f*gws;
            if (t < 256){
                int b = t>>3, part = t&7;
                float acc = 0.f;
                #pragma unroll 8
                for (int i=0;i<64;i++){
                    int k = part + (i<<3);
                    float a = As[b*516 + k];
                    float wv = gateW[k];
                    float qv = fminf(fmaxf(rintf(a*inv), -128.f), 127.f);
                    acc += terx(qv, wv, thr);
                }
                gs[t] = acc;
            }
            __syncthreads();
            if (t < 32){
                float d = 0.f;
                #pragma unroll
                for (int p=0;p<8;p++) d += gs[t*8+p];
                float z = d*gws*is + gateB[0];
                ((int*)aux)[1+t] = (z < 0.f) ? 1 : 0;  // sigmoid(z)<0.5 <=> z<0
            }
            __syncthreads();
            if (t==0){
                int all = 1;
                #pragma unroll
                for (int b2=0;b2<32;b2++) all &= ((int*)aux)[1+b2];
                g_trig[step-1] = all;                  // idempotent across blocks
                float wv = 1.f;
                for (int s2=3; s2<step; s2++){
                    int tv = (s2==step-1) ? all : g_trig[s2];
                    if (tv) wv = 0.f;
                }
                aux[0] = wv;
            }
            __syncthreads();
        } else {
            if (t==0) aux[0] = 1.f;
            __syncthreads();
        }
        float wsv = aux[0];

        // GEMM: warp covers 2 cols, K split across warp pairs; packed f32x2 FMA
        int cg = w>>1, half = w&1;
        int r0 = blk*4;
        int c0 = cg*2, c1 = c0+1;
        int j0 = r0 + (c0>>2) + ((c0&3)<<9);
        int j1 = r0 + (c1>>2) + ((c1&3)<<9);
        const ulonglong2* W0 = (const ulonglong2*)(Wp + j0*RR);
        const ulonglong2* W1 = (const ulonglong2*)(Wp + j1*RR);
        const ulonglong2* a8 = (const ulonglong2*)(As + lane*516);
        unsigned long long p0=0ull,p1=0ull,q0=0ull,q1=0ull;
        int h0 = half*64;
        #pragma unroll 8
        for (int k=h0; k<h0+64; k++){
            ulonglong2 av = a8[k];
            ulonglong2 w0 = W0[k], w1 = W1[k];
            fma2(p0, av.x, w0.x); fma2(p1, av.y, w0.y);
            fma2(q0, av.x, w1.x); fma2(q1, av.y, w1.y);
        }
        gs[(c0*32+lane)*2+half] = f2sum(p0) + f2sum(p1);
        gs[(c1*32+lane)*2+half] = f2sum(q0) + f2sum(q1);
        __syncthreads();

        // epilogue
        float hh_abs = 0.f, hs_abs = 0.f;
        if (t < 128){
            int b = t&31, rr = t>>5;
            int r = r0 + rr;
            float gi = gs[((rr*4+0)*32+b)*2] + gs[((rr*4+0)*32+b)*2+1] + bih[r]      + bhh[r];
            float gf = gs[((rr*4+1)*32+b)*2] + gs[((rr*4+1)*32+b)*2+1] + bih[r+512]  + bhh[r+512];
            float gg = gs[((rr*4+2)*32+b)*2] + gs[((rr*4+2)*32+b)*2+1] + bih[r+1024] + bhh[r+1024];
            float go = gs[((rr*4+3)*32+b)*2] + gs[((rr*4+3)*32+b)*2+1] + bih[r+1536] + bhh[r+1536];
            int idx = b*RR + r;
            float cn = sigm(gf)*g_c[idx] + sigm(gi)*tanhf(gg);
            float hh = sigm(go)*tanhf(cn);
            g_c[idx] = cn;
            g_h[idx] = hh;
            float hs = g_hsum[idx] + wsv * hh;
            g_hsum[idx] = hs;
            hh_abs = fabsf(hh);
            hs_abs = fabsf(hs);
        }
        float m = warpRedMax(hh_abs);
        if (lane==0) aux[44+w] = m;
        float m2 = warpRedMax(hs_abs);
        if (lane==0) aux[28+w] = m2;
        __syncthreads();
        if (t==0){
            float mm = fmaxf(fmaxf(aux[44],aux[45]), fmaxf(aux[46],aux[47]));
            g_maxh_p[step][blk] = mm;             // per-block slot
            if (step == NSTEPS-1){
                float mh = fmaxf(fmaxf(aux[28],aux[29]), fmaxf(aux[30],aux[31]));
                g_maxhsum_p[blk] = mh;
            }
        }
        gbar(t, blk, fbase+3+step);
    }

    // ===== phase 10: dec  rout = bit_linear(hsum/ws) via dp4a (final folded in) =====
    {
        float wgt = 1.f, ws = 0.f;
        #pragma unroll
        for (int s=0;s<NSTEPS;s++){
            ws += wgt;
            if (s>=3 && s<=6 && g_trig[s]) wgt = 0.f;
        }
        float inv = 1.f/ws;
        // reduce per-block |hsum| maxes
        float mv = 0.f;
        if (t < MIDG) mv = g_maxhsum_p[t];
        mv = warpRedMax(mv);
        if (lane==0 && w < 4) aux[40+w] = mv;
        __syncthreads();
        float is = fmaxf(fmaxf(aux[40],aux[41]),fmaxf(aux[42],aux[43])) * inv * (1.f/127.f);

        int* smq = (int*)sm;                      // [32][129] words
        for (int i4=t; i4<4096; i4+=MIDT){
            float4 v = ((const float4*)g_hsum)[i4];
            smq[(i4>>7)*129 + (i4&127)] =
                pack4((int)quantz(v.x*inv,is), (int)quantz(v.y*inv,is),
                      (int)quantz(v.z*inv,is), (int)quantz(v.w*inv,is));
        }
        __syncthreads();
        float ssum = 0.f;
        #pragma unroll
        for (int i=0;i<32;i++) ssum += g_decpart[i];
        float wscale = ssum * (1.f/524288.f);
        int r = blk*8 + (w>>1);                   // 8 rows/block, 2 warps/row (K-split)
        int half = w & 1;
        const int4* Wq = (const int4*)(g_decQ + r*128 + half*64);
        const int*  ar = smq + lane*129 + half*64;
        int a0=0,a1=0,a2=0,a3=0;
        #pragma unroll
        for (int k=0;k<16;k++){
            int4 wv = Wq[k];
            a0 = __dp4a(ar[4*k+0], wv.x, a0);
            a1 = __dp4a(ar[4*k+1], wv.y, a1);
            a2 = __dp4a(ar[4*k+2], wv.z, a2);
            a3 = __dp4a(ar[4*k+3], wv.w, a3);
        }
        int* sp = (int*)(sm + 4608);              // 512 ints
        sp[((w>>1)*32+lane)*2 + half] = (a0+a1)+(a2+a3);
        __syncthreads();
        if (t < 256){
            int rr = t>>5, b = t&31;              // rr 0..7
            int s = sp[(rr*32+b)*2] + sp[(rr*32+b)*2+1];
            g_rout[b*EE + blk*8+rr] = (float)s*(wscale*is) + decB[blk*8+rr];
        }
    }
}

// ---------------- K_add: out = x + rout (broadcast over seq, streaming) ----------------
__global__ void k_add(const float* __restrict__ x, float* __restrict__ out){
    size_t i = (size_t)blockIdx.x*256 + threadIdx.x;   // float4 index, 16777216 total
    float4 xv = __ldcs((const float4*)x + i);
    int e4 = (int)(i & 255);
    int b  = (int)(i >> 19);
    float4 r = ((const float4*)g_rout)[(b<<8) + e4];
    float4 o; o.x=xv.x+r.x; o.y=xv.y+r.y; o.z=xv.z+r.z; o.w=xv.w+r.w;
    __stcs((float4*)out + i, o);
}

// ---------------- launch ----------------
extern "C" void kernel_launch(void* const* d_in, const int* in_sizes, int n_in,
                              void* d_out, int out_size){
    const float* x    = (const float*)d_in[0];
    const float* encW = (const float*)d_in[1];
    const float* encB = (const float*)d_in[2];
    const float* Wih  = (const float*)d_in[3];
    const float* Whh  = (const float*)d_in[4];
    const float* bih  = (const float*)d_in[5];
    const float* bhh  = (const float*)d_in[6];
    const float* decW = (const float*)d_in[7];
    const float* decB = (const float*)d_in[8];
    const float* gtW  = (const float*)d_in[9];
    const float* gtB  = (const float*)d_in[10];
    float* out = (float*)d_out;

    cudaFuncSetAttribute(k_mid, cudaFuncAttributeMaxDynamicSharedMemorySize, MID_SMEM);

    k_init <<<1089, 256>>>(Wih, Whh, encW, decW, gtW);
    k_mid  <<<MIDG, MIDT, MID_SMEM>>>(x, encW, encB, Wih, bih, bhh, decW, decB, gtW, gtB);
    k_add  <<<65536, 256>>>(x, out);
}